// round 2
// baseline (speedup 1.0000x reference)
#include <cuda_runtime.h>
#include <cuda_bf16.h>
#include <cstdint>

// Inputs (metadata order):
//   d_in[0] weight : float32 [N_NODES * 128]
//   d_in[1] cj     : float32 [N_NODES]
//   d_in[2] ci     : float32 [N_NODES]
//   d_in[3] src    : int32   [N_EDGES]
//   d_in[4] dst    : int32   [N_EDGES]
// Output: float32 [N_NODES * 128]
//
// h = segment_sum_{e}( (weight[src_e] * cj[src_e]) , dst_e ) * ci
//   = segment_sum_{e}( weight[src_e] * cj[src_e] * ci[dst_e] , dst_e )
// so ci folds into the per-edge scale and we need only zero-init + one
// scatter kernel with vector atomics.

static constexpr int FEAT4 = 32;  // 128 floats = 32 float4 per row

__device__ __forceinline__ void red_add_v4(float4* addr, float4 v) {
    asm volatile(
        "red.global.add.v4.f32 [%0], {%1, %2, %3, %4};"
        :: "l"(addr), "f"(v.x), "f"(v.y), "f"(v.z), "f"(v.w)
        : "memory");
}

__global__ void gcmc_scatter_kernel(
    const float4* __restrict__ weight4,
    const float*  __restrict__ cj,
    const float*  __restrict__ ci,
    const int*    __restrict__ src,
    const int*    __restrict__ dst,
    float4*       __restrict__ out4,
    int n_edges)
{
    // One warp per edge; lane c handles float4 chunk c (c in [0,32)).
    int64_t gidx = (int64_t)blockIdx.x * blockDim.x + threadIdx.x;
    int e = (int)(gidx >> 5);
    int c = (int)(gidx & 31);
    if (e >= n_edges) return;

    int s = __ldg(src + e);
    int d = __ldg(dst + e);
    float scale = __ldg(cj + s) * __ldg(ci + d);

    float4 v = __ldg(weight4 + (int64_t)s * FEAT4 + c);
    v.x *= scale; v.y *= scale; v.z *= scale; v.w *= scale;

    red_add_v4(out4 + (int64_t)d * FEAT4 + c, v);
}

extern "C" void kernel_launch(void* const* d_in, const int* in_sizes, int n_in,
                              void* d_out, int out_size)
{
    const float4* weight4 = (const float4*)d_in[0];
    const float*  cj      = (const float*)d_in[1];
    const float*  ci      = (const float*)d_in[2];
    const int*    src     = (const int*)d_in[3];
    const int*    dst     = (const int*)d_in[4];
    float4*       out4    = (float4*)d_out;

    int n_edges = in_sizes[3];

    // Output is poisoned; zero it (captured async memset is graph-legal).
    cudaMemsetAsync(d_out, 0, (size_t)out_size * sizeof(float), 0);

    // One warp (32 lanes) per edge.
    int64_t total_threads = (int64_t)n_edges * 32;
    int block = 256;
    int64_t grid = (total_threads + block - 1) / block;
    gcmc_scatter_kernel<<<(unsigned)grid, block>>>(
        weight4, cj, ci, src, dst, out4, n_edges);
}

// round 3
// speedup vs baseline: 2.0832x; 2.0832x over previous
#include <cuda_runtime.h>
#include <cuda_bf16.h>
#include <cstdint>

// Inputs (metadata order):
//   d_in[0] weight : float32 [N_NODES * 128]
//   d_in[1] cj     : float32 [N_NODES]
//   d_in[2] ci     : float32 [N_NODES]
//   d_in[3] src    : int32   [N_EDGES]
//   d_in[4] dst    : int32   [N_EDGES]
// Output: float32 [N_NODES * 128]
//
// h[d] = ci[d] * sum_{e: dst_e = d} weight[src_e] * cj[src_e]
//
// Strategy: build a dst-CSR per call (histogram + scan + scatter into a
// __device__ scratch edge list), then one warp per destination node
// accumulates its in-edges in registers and does a single 512B store.
// This removes all float atomics (819MB of L2 RMW traffic in the previous
// version) and the output memset.

static constexpr int MAX_NODES  = 100000;
static constexpr int MAX_EDGES  = 1600000;
static constexpr int FEAT4      = 32;           // 128 floats = 32 float4
static constexpr int SCAN_BLOCK = 1024;
static constexpr int MAX_SCAN_BLOCKS = (MAX_NODES + SCAN_BLOCK - 1) / SCAN_BLOCK; // 98

__device__ int g_counts[MAX_NODES];
__device__ int g_offsets[MAX_NODES];
__device__ int g_cursor[MAX_NODES];
__device__ int g_blocksums[MAX_SCAN_BLOCKS + 1];
__device__ int g_edge_src[MAX_EDGES];

// ---------------- CSR build ----------------

__global__ void k_zero_counts(int n) {
    int i = blockIdx.x * blockDim.x + threadIdx.x;
    if (i < n) g_counts[i] = 0;
}

__global__ void k_hist(const int* __restrict__ dst, int n_edges) {
    int e = blockIdx.x * blockDim.x + threadIdx.x;
    if (e < n_edges) atomicAdd(&g_counts[dst[e]], 1);
}

// Block-local exclusive scan of g_counts -> g_offsets, block totals -> g_blocksums
__global__ void k_scan1(int n) {
    __shared__ int warp_sums[32];
    int tid  = threadIdx.x;
    int i    = blockIdx.x * SCAN_BLOCK + tid;
    int lane = tid & 31, wid = tid >> 5;

    int v = (i < n) ? g_counts[i] : 0;

    // inclusive warp scan
    int x = v;
    #pragma unroll
    for (int o = 1; o < 32; o <<= 1) {
        int y = __shfl_up_sync(0xFFFFFFFFu, x, o);
        if (lane >= o) x += y;
    }
    if (lane == 31) warp_sums[wid] = x;
    __syncthreads();

    if (wid == 0) {
        int w = warp_sums[lane];
        #pragma unroll
        for (int o = 1; o < 32; o <<= 1) {
            int y = __shfl_up_sync(0xFFFFFFFFu, w, o);
            if (lane >= o) w += y;
        }
        warp_sums[lane] = w;   // inclusive sums of warp totals
    }
    __syncthreads();

    int warp_off = (wid > 0) ? warp_sums[wid - 1] : 0;
    if (i < n) g_offsets[i] = warp_off + x - v;     // exclusive within block
    if (tid == 0) g_blocksums[blockIdx.x] = warp_sums[31];  // block total
}

// Sequential exclusive scan over block totals (<=98 elements; trivial)
__global__ void k_scan2(int nblocks) {
    if (threadIdx.x == 0 && blockIdx.x == 0) {
        int acc = 0;
        for (int b = 0; b < nblocks; b++) {
            int t = g_blocksums[b];
            g_blocksums[b] = acc;
            acc += t;
        }
    }
}

// Add block offsets; also initialize cursor = offsets for the scatter pass.
__global__ void k_scan3(int n) {
    int i = blockIdx.x * blockDim.x + threadIdx.x;
    if (i < n) {
        int o = g_offsets[i] + g_blocksums[i / SCAN_BLOCK];
        g_offsets[i] = o;
        g_cursor[i]  = o;
    }
}

// Scatter src ids into dst-sorted edge list.
__global__ void k_scatter(const int* __restrict__ src,
                          const int* __restrict__ dst, int n_edges) {
    int e = blockIdx.x * blockDim.x + threadIdx.x;
    if (e < n_edges) {
        int d = dst[e];
        int p = atomicAdd(&g_cursor[d], 1);
        g_edge_src[p] = src[e];
    }
}

// ---------------- main gather-accumulate ----------------
// One warp per destination node; lane c owns float4 chunk c of the 128-wide row.

__global__ void __launch_bounds__(256)
k_gather(const float4* __restrict__ weight4,
         const float*  __restrict__ cj,
         const float*  __restrict__ ci,
         float4*       __restrict__ out4,
         int n_nodes)
{
    int gid  = blockIdx.x * blockDim.x + threadIdx.x;
    int node = gid >> 5;
    int c    = gid & 31;
    if (node >= n_nodes) return;

    int base = g_offsets[node];
    int cnt  = g_counts[node];

    float4 acc = make_float4(0.f, 0.f, 0.f, 0.f);

    int j = 0;
    // unroll by 2 for memory-level parallelism on the gathers
    for (; j + 1 < cnt; j += 2) {
        int s0 = g_edge_src[base + j];       // uniform per warp -> broadcast
        int s1 = g_edge_src[base + j + 1];
        float sc0 = __ldg(cj + s0);
        float sc1 = __ldg(cj + s1);
        float4 v0 = __ldg(weight4 + (int64_t)s0 * FEAT4 + c);
        float4 v1 = __ldg(weight4 + (int64_t)s1 * FEAT4 + c);
        acc.x += v0.x * sc0; acc.y += v0.y * sc0;
        acc.z += v0.z * sc0; acc.w += v0.w * sc0;
        acc.x += v1.x * sc1; acc.y += v1.y * sc1;
        acc.z += v1.z * sc1; acc.w += v1.w * sc1;
    }
    if (j < cnt) {
        int s0 = g_edge_src[base + j];
        float sc0 = __ldg(cj + s0);
        float4 v0 = __ldg(weight4 + (int64_t)s0 * FEAT4 + c);
        acc.x += v0.x * sc0; acc.y += v0.y * sc0;
        acc.z += v0.z * sc0; acc.w += v0.w * sc0;
    }

    float m = __ldg(ci + node);
    acc.x *= m; acc.y *= m; acc.z *= m; acc.w *= m;
    out4[(int64_t)node * FEAT4 + c] = acc;   // every node written: no memset needed
}

// ---------------- launch ----------------

extern "C" void kernel_launch(void* const* d_in, const int* in_sizes, int n_in,
                              void* d_out, int out_size)
{
    const float4* weight4 = (const float4*)d_in[0];
    const float*  cj      = (const float*)d_in[1];
    const float*  ci      = (const float*)d_in[2];
    const int*    src     = (const int*)d_in[3];
    const int*    dst     = (const int*)d_in[4];
    float4*       out4    = (float4*)d_out;

    int n_nodes = in_sizes[1];   // cj is [N,1]
    int n_edges = in_sizes[3];

    const int B = 256;
    int node_blocks = (n_nodes + B - 1) / B;
    int edge_blocks = (n_edges + B - 1) / B;
    int scan_blocks = (n_nodes + SCAN_BLOCK - 1) / SCAN_BLOCK;

    k_zero_counts<<<node_blocks, B>>>(n_nodes);
    k_hist<<<edge_blocks, B>>>(dst, n_edges);
    k_scan1<<<scan_blocks, SCAN_BLOCK>>>(n_nodes);
    k_scan2<<<1, 32>>>(scan_blocks);
    k_scan3<<<node_blocks, B>>>(n_nodes);
    k_scatter<<<edge_blocks, B>>>(src, dst, n_edges);

    // 32 lanes per node
    int64_t total_threads = (int64_t)n_nodes * 32;
    int gather_blocks = (int)((total_threads + B - 1) / B);
    k_gather<<<gather_blocks, B>>>(weight4, cj, ci, out4, n_nodes);
}

// round 4
// speedup vs baseline: 2.2518x; 1.0810x over previous
#include <cuda_runtime.h>
#include <cuda_bf16.h>
#include <cstdint>

// Inputs (metadata order):
//   d_in[0] weight : float32 [N_NODES * 128]
//   d_in[1] cj     : float32 [N_NODES]
//   d_in[2] ci     : float32 [N_NODES]
//   d_in[3] src    : int32   [N_EDGES]
//   d_in[4] dst    : int32   [N_EDGES]
// Output: float32 [N_NODES * 128]
//
// h[d] = ci[d] * sum_{e: dst_e = d} weight[src_e] * cj[src_e]
//
// Pipeline: zero counts -> int4 histogram of dst -> block-local scan ->
// fused (cross-block prefix + offset/cursor write) -> int4 scatter of src
// into dst-sorted order -> warp-per-node register-accumulate gather.

static constexpr int MAX_NODES  = 100000;
static constexpr int MAX_EDGES  = 1600000;
static constexpr int FEAT4      = 32;           // 128 floats = 32 float4
static constexpr int SCAN_BLOCK = 1024;
static constexpr int MAX_SCAN_BLOCKS = (MAX_NODES + SCAN_BLOCK - 1) / SCAN_BLOCK; // 98

__device__ int g_counts[MAX_NODES];
__device__ int g_offsets[MAX_NODES];
__device__ int g_cursor[MAX_NODES];
__device__ int g_blocksums[MAX_SCAN_BLOCKS + 1];
__device__ int g_edge_src[MAX_EDGES];

// ---------------- CSR build ----------------

__global__ void k_zero_counts(int n) {
    int i = blockIdx.x * blockDim.x + threadIdx.x;
    if (i < n) g_counts[i] = 0;
}

// 4 edges per thread via int4 loads.
__global__ void k_hist(const int4* __restrict__ dst4, int n_quads,
                       const int* __restrict__ dst, int n_edges) {
    int q = blockIdx.x * blockDim.x + threadIdx.x;
    if (q < n_quads) {
        int4 d = __ldg(dst4 + q);
        atomicAdd(&g_counts[d.x], 1);
        atomicAdd(&g_counts[d.y], 1);
        atomicAdd(&g_counts[d.z], 1);
        atomicAdd(&g_counts[d.w], 1);
    }
    // tail (n_edges % 4) handled by the first few threads of block 0
    int t = n_quads * 4 + q;
    if (q < (n_edges - n_quads * 4)) atomicAdd(&g_counts[dst[t]], 1);
}

// Block-local exclusive scan of g_counts -> g_offsets, block totals -> g_blocksums
__global__ void k_scan1(int n) {
    __shared__ int warp_sums[32];
    int tid  = threadIdx.x;
    int i    = blockIdx.x * SCAN_BLOCK + tid;
    int lane = tid & 31, wid = tid >> 5;

    int v = (i < n) ? g_counts[i] : 0;

    int x = v;  // inclusive warp scan
    #pragma unroll
    for (int o = 1; o < 32; o <<= 1) {
        int y = __shfl_up_sync(0xFFFFFFFFu, x, o);
        if (lane >= o) x += y;
    }
    if (lane == 31) warp_sums[wid] = x;
    __syncthreads();

    if (wid == 0) {
        int w = warp_sums[lane];
        #pragma unroll
        for (int o = 1; o < 32; o <<= 1) {
            int y = __shfl_up_sync(0xFFFFFFFFu, w, o);
            if (lane >= o) w += y;
        }
        warp_sums[lane] = w;   // inclusive sums of warp totals
    }
    __syncthreads();

    int warp_off = (wid > 0) ? warp_sums[wid - 1] : 0;
    if (i < n) g_offsets[i] = warp_off + x - v;              // exclusive within block
    if (tid == 0) g_blocksums[blockIdx.x] = warp_sums[31];   // block total
}

// Fused cross-block prefix + global offset write + cursor init.
// Each 256-thread block covers 256 nodes, all inside ONE 1024-node scan chunk
// (256 divides 1024 and blocks are aligned), so the whole block shares a
// single prefix: sum of g_blocksums[0 .. chunk). Warp 0 reduces it (<=98 ints).
__global__ void __launch_bounds__(256)
k_scan3(int n) {
    __shared__ int s_prefix;
    int chunk = (blockIdx.x * 256) / SCAN_BLOCK;

    if (threadIdx.x < 32) {
        int acc = 0;
        for (int b = threadIdx.x; b < chunk; b += 32) acc += g_blocksums[b];
        #pragma unroll
        for (int o = 16; o > 0; o >>= 1)
            acc += __shfl_down_sync(0xFFFFFFFFu, acc, o);
        if (threadIdx.x == 0) s_prefix = acc;
    }
    __syncthreads();

    int i = blockIdx.x * 256 + threadIdx.x;
    if (i < n) {
        int o = g_offsets[i] + s_prefix;
        g_offsets[i] = o;
        g_cursor[i]  = o;
    }
}

// Scatter src ids into dst-sorted edge list; 4 edges per thread.
__global__ void k_scatter(const int4* __restrict__ src4,
                          const int4* __restrict__ dst4, int n_quads,
                          const int* __restrict__ src,
                          const int* __restrict__ dst, int n_edges) {
    int q = blockIdx.x * blockDim.x + threadIdx.x;
    if (q < n_quads) {
        int4 s = __ldg(src4 + q);
        int4 d = __ldg(dst4 + q);
        g_edge_src[atomicAdd(&g_cursor[d.x], 1)] = s.x;
        g_edge_src[atomicAdd(&g_cursor[d.y], 1)] = s.y;
        g_edge_src[atomicAdd(&g_cursor[d.z], 1)] = s.z;
        g_edge_src[atomicAdd(&g_cursor[d.w], 1)] = s.w;
    }
    int t = n_quads * 4 + q;
    if (q < (n_edges - n_quads * 4))
        g_edge_src[atomicAdd(&g_cursor[dst[t]], 1)] = src[t];
}

// ---------------- main gather-accumulate ----------------
// One warp per destination node; lane c owns float4 chunk c of the 128-wide row.

__global__ void __launch_bounds__(256)
k_gather(const float4* __restrict__ weight4,
         const float*  __restrict__ cj,
         const float*  __restrict__ ci,
         float4*       __restrict__ out4,
         int n_nodes)
{
    int gid  = blockIdx.x * blockDim.x + threadIdx.x;
    int node = gid >> 5;
    int c    = gid & 31;
    if (node >= n_nodes) return;

    int base = g_offsets[node];
    int cnt  = g_counts[node];

    float4 acc = make_float4(0.f, 0.f, 0.f, 0.f);

    int j = 0;
    // unroll by 4: four independent gathers in flight per warp
    for (; j + 3 < cnt; j += 4) {
        int s0 = g_edge_src[base + j];
        int s1 = g_edge_src[base + j + 1];
        int s2 = g_edge_src[base + j + 2];
        int s3 = g_edge_src[base + j + 3];
        float sc0 = __ldg(cj + s0);
        float sc1 = __ldg(cj + s1);
        float sc2 = __ldg(cj + s2);
        float sc3 = __ldg(cj + s3);
        float4 v0 = __ldg(weight4 + (int64_t)s0 * FEAT4 + c);
        float4 v1 = __ldg(weight4 + (int64_t)s1 * FEAT4 + c);
        float4 v2 = __ldg(weight4 + (int64_t)s2 * FEAT4 + c);
        float4 v3 = __ldg(weight4 + (int64_t)s3 * FEAT4 + c);
        acc.x += v0.x * sc0; acc.y += v0.y * sc0; acc.z += v0.z * sc0; acc.w += v0.w * sc0;
        acc.x += v1.x * sc1; acc.y += v1.y * sc1; acc.z += v1.z * sc1; acc.w += v1.w * sc1;
        acc.x += v2.x * sc2; acc.y += v2.y * sc2; acc.z += v2.z * sc2; acc.w += v2.w * sc2;
        acc.x += v3.x * sc3; acc.y += v3.y * sc3; acc.z += v3.z * sc3; acc.w += v3.w * sc3;
    }
    for (; j < cnt; j++) {
        int s0 = g_edge_src[base + j];
        float sc0 = __ldg(cj + s0);
        float4 v0 = __ldg(weight4 + (int64_t)s0 * FEAT4 + c);
        acc.x += v0.x * sc0; acc.y += v0.y * sc0; acc.z += v0.z * sc0; acc.w += v0.w * sc0;
    }

    float m = __ldg(ci + node);
    acc.x *= m; acc.y *= m; acc.z *= m; acc.w *= m;
    out4[(int64_t)node * FEAT4 + c] = acc;   // every node written: no memset needed
}

// ---------------- launch ----------------

extern "C" void kernel_launch(void* const* d_in, const int* in_sizes, int n_in,
                              void* d_out, int out_size)
{
    const float4* weight4 = (const float4*)d_in[0];
    const float*  cj      = (const float*)d_in[1];
    const float*  ci      = (const float*)d_in[2];
    const int*    src     = (const int*)d_in[3];
    const int*    dst     = (const int*)d_in[4];
    float4*       out4    = (float4*)d_out;

    int n_nodes = in_sizes[1];   // cj is [N,1]
    int n_edges = in_sizes[3];
    int n_quads = n_edges / 4;

    const int B = 256;
    int node_blocks = (n_nodes + B - 1) / B;
    int quad_blocks = (n_quads + B - 1) / B;
    int scan_blocks = (n_nodes + SCAN_BLOCK - 1) / SCAN_BLOCK;

    k_zero_counts<<<node_blocks, B>>>(n_nodes);
    k_hist<<<quad_blocks, B>>>((const int4*)dst, n_quads, dst, n_edges);
    k_scan1<<<scan_blocks, SCAN_BLOCK>>>(n_nodes);
    k_scan3<<<node_blocks, B>>>(n_nodes);
    k_scatter<<<quad_blocks, B>>>((const int4*)src, (const int4*)dst, n_quads,
                                  src, dst, n_edges);

    int64_t total_threads = (int64_t)n_nodes * 32;
    int gather_blocks = (int)((total_threads + B - 1) / B);
    k_gather<<<gather_blocks, B>>>(weight4, cj, ci, out4, n_nodes);
}

// round 5
// speedup vs baseline: 2.3938x; 1.0630x over previous
#include <cuda_runtime.h>
#include <cuda_bf16.h>
#include <cstdint>

// Inputs (metadata order):
//   d_in[0] weight : float32 [N_NODES * 128]
//   d_in[1] cj     : float32 [N_NODES]
//   d_in[2] ci     : float32 [N_NODES]
//   d_in[3] src    : int32   [N_EDGES]
//   d_in[4] dst    : int32   [N_EDGES]
// Output: float32 [N_NODES * 128]
//
// h[d] = ci[d] * sum_{e: dst_e = d} weight[src_e] * cj[src_e]
//
// 4-kernel pipeline:
//   k_hist    : int4 histogram of dst into g_counts (counts start zero;
//               the gather epilogue re-zeroes them for the next replay)
//   k_scan    : fused exclusive scan of g_counts -> g_offsets/g_cursor.
//               98 co-resident blocks; cross-block prefix via packed
//               publish/poll words (reset by k_scatter for next replay)
//   k_scatter : scatter src ids into dst-sorted g_edge_src via g_cursor
//   k_gather  : one warp per dst node, register accumulation, single store

static constexpr int MAX_NODES  = 100000;
static constexpr int MAX_EDGES  = 1600000;
static constexpr int FEAT4      = 32;           // 128 floats = 32 float4
static constexpr int SCAN_BLOCK = 1024;
static constexpr int MAX_SCAN_BLOCKS = (MAX_NODES + SCAN_BLOCK - 1) / SCAN_BLOCK; // 98

__device__ int g_counts[MAX_NODES];             // zero-init; restored by gather
__device__ int g_offsets[MAX_NODES];
__device__ int g_cursor[MAX_NODES];
__device__ unsigned int g_pub[MAX_SCAN_BLOCKS]; // zero-init; restored by scatter
__device__ int g_edge_src[MAX_EDGES];

// ---------------- histogram ----------------

__global__ void k_hist(const int4* __restrict__ dst4, int n_quads,
                       const int* __restrict__ dst, int n_edges) {
    int q = blockIdx.x * blockDim.x + threadIdx.x;
    if (q < n_quads) {
        int4 d = __ldg(dst4 + q);
        atomicAdd(&g_counts[d.x], 1);
        atomicAdd(&g_counts[d.y], 1);
        atomicAdd(&g_counts[d.z], 1);
        atomicAdd(&g_counts[d.w], 1);
    }
    int t = n_quads * 4 + q;
    if (q < (n_edges - n_quads * 4)) atomicAdd(&g_counts[dst[t]], 1);
}

// ---------------- fused exclusive scan ----------------
// Grid = ceil(n/1024) = 98 blocks of 1024 threads: all co-resident on 148 SMs,
// so publish/poll across blocks cannot deadlock. Each block publishes its
// chunk total as (0x80000000 | total); totals < 2^31 so bit31 is the flag.

__global__ void __launch_bounds__(SCAN_BLOCK)
k_scan(int n) {
    __shared__ int warp_sums[32];
    __shared__ int s_prefix;
    int tid  = threadIdx.x;
    int i    = blockIdx.x * SCAN_BLOCK + tid;
    int lane = tid & 31, wid = tid >> 5;

    int v = (i < n) ? g_counts[i] : 0;

    // inclusive warp scan
    int x = v;
    #pragma unroll
    for (int o = 1; o < 32; o <<= 1) {
        int y = __shfl_up_sync(0xFFFFFFFFu, x, o);
        if (lane >= o) x += y;
    }
    if (lane == 31) warp_sums[wid] = x;
    __syncthreads();

    if (wid == 0) {
        int w = warp_sums[lane];
        #pragma unroll
        for (int o = 1; o < 32; o <<= 1) {
            int y = __shfl_up_sync(0xFFFFFFFFu, w, o);
            if (lane >= o) w += y;
        }
        warp_sums[lane] = w;                 // inclusive sums of warp totals
        if (lane == 31) {
            // publish this block's total (flag packed in bit31)
            atomicExch(&g_pub[blockIdx.x], 0x80000000u | (unsigned)w);
        }
    }
    __syncthreads();

    // warp 0: sum aggregates of all predecessor blocks (spin until published)
    if (wid == 0) {
        int acc = 0;
        for (int b = lane; b < (int)blockIdx.x; b += 32) {
            unsigned int p;
            do {
                p = *(volatile unsigned int*)&g_pub[b];
            } while (!(p & 0x80000000u));
            acc += (int)(p & 0x7FFFFFFFu);
        }
        #pragma unroll
        for (int o = 16; o > 0; o >>= 1)
            acc += __shfl_down_sync(0xFFFFFFFFu, acc, o);
        if (lane == 0) s_prefix = acc;
    }
    __syncthreads();

    int warp_off = (wid > 0) ? warp_sums[wid - 1] : 0;
    if (i < n) {
        int o = s_prefix + warp_off + x - v;   // global exclusive prefix
        g_offsets[i] = o;
        g_cursor[i]  = o;
    }
}

// ---------------- scatter ----------------

__global__ void k_scatter(const int4* __restrict__ src4,
                          const int4* __restrict__ dst4, int n_quads,
                          const int* __restrict__ src,
                          const int* __restrict__ dst, int n_edges) {
    int q = blockIdx.x * blockDim.x + threadIdx.x;
    if (q < n_quads) {
        int4 s = __ldg(src4 + q);
        int4 d = __ldg(dst4 + q);
        g_edge_src[atomicAdd(&g_cursor[d.x], 1)] = s.x;
        g_edge_src[atomicAdd(&g_cursor[d.y], 1)] = s.y;
        g_edge_src[atomicAdd(&g_cursor[d.z], 1)] = s.z;
        g_edge_src[atomicAdd(&g_cursor[d.w], 1)] = s.w;
    }
    int t = n_quads * 4 + q;
    if (q < (n_edges - n_quads * 4))
        g_edge_src[atomicAdd(&g_cursor[dst[t]], 1)] = src[t];

    // reset scan publish flags for the next graph replay
    if (blockIdx.x == 0 && threadIdx.x < MAX_SCAN_BLOCKS)
        g_pub[threadIdx.x] = 0u;
}

// ---------------- main gather-accumulate ----------------
// One warp per destination node; lane c owns float4 chunk c of the 128-wide row.
// After k_scatter, g_cursor[node] == g_offsets[node] + in_degree(node).

__global__ void __launch_bounds__(256)
k_gather(const float4* __restrict__ weight4,
         const float*  __restrict__ cj,
         const float*  __restrict__ ci,
         float4*       __restrict__ out4,
         int n_nodes)
{
    int gid  = blockIdx.x * blockDim.x + threadIdx.x;
    int node = gid >> 5;
    int c    = gid & 31;
    if (node >= n_nodes) return;

    int base = g_offsets[node];
    int end  = g_cursor[node];

    float4 acc = make_float4(0.f, 0.f, 0.f, 0.f);

    int j = base;
    for (; j + 3 < end; j += 4) {
        int s0 = g_edge_src[j];
        int s1 = g_edge_src[j + 1];
        int s2 = g_edge_src[j + 2];
        int s3 = g_edge_src[j + 3];
        float sc0 = __ldg(cj + s0);
        float sc1 = __ldg(cj + s1);
        float sc2 = __ldg(cj + s2);
        float sc3 = __ldg(cj + s3);
        float4 v0 = __ldg(weight4 + (int64_t)s0 * FEAT4 + c);
        float4 v1 = __ldg(weight4 + (int64_t)s1 * FEAT4 + c);
        float4 v2 = __ldg(weight4 + (int64_t)s2 * FEAT4 + c);
        float4 v3 = __ldg(weight4 + (int64_t)s3 * FEAT4 + c);
        acc.x += v0.x * sc0; acc.y += v0.y * sc0; acc.z += v0.z * sc0; acc.w += v0.w * sc0;
        acc.x += v1.x * sc1; acc.y += v1.y * sc1; acc.z += v1.z * sc1; acc.w += v1.w * sc1;
        acc.x += v2.x * sc2; acc.y += v2.y * sc2; acc.z += v2.z * sc2; acc.w += v2.w * sc2;
        acc.x += v3.x * sc3; acc.y += v3.y * sc3; acc.z += v3.z * sc3; acc.w += v3.w * sc3;
    }
    for (; j < end; j++) {
        int s0 = g_edge_src[j];
        float sc0 = __ldg(cj + s0);
        float4 v0 = __ldg(weight4 + (int64_t)s0 * FEAT4 + c);
        acc.x += v0.x * sc0; acc.y += v0.y * sc0; acc.z += v0.z * sc0; acc.w += v0.w * sc0;
    }

    float m = __ldg(ci + node);
    acc.x *= m; acc.y *= m; acc.z *= m; acc.w *= m;
    out4[(int64_t)node * FEAT4 + c] = acc;

    // restore the zero-counts invariant for the next graph replay
    if (c == 0) g_counts[node] = 0;
}

// ---------------- launch ----------------

extern "C" void kernel_launch(void* const* d_in, const int* in_sizes, int n_in,
                              void* d_out, int out_size)
{
    const float4* weight4 = (const float4*)d_in[0];
    const float*  cj      = (const float*)d_in[1];
    const float*  ci      = (const float*)d_in[2];
    const int*    src     = (const int*)d_in[3];
    const int*    dst     = (const int*)d_in[4];
    float4*       out4    = (float4*)d_out;

    int n_nodes = in_sizes[1];   // cj is [N,1]
    int n_edges = in_sizes[3];
    int n_quads = n_edges / 4;

    const int B = 256;
    int quad_blocks = (n_quads + B - 1) / B;
    int scan_blocks = (n_nodes + SCAN_BLOCK - 1) / SCAN_BLOCK;

    k_hist<<<quad_blocks, B>>>((const int4*)dst, n_quads, dst, n_edges);
    k_scan<<<scan_blocks, SCAN_BLOCK>>>(n_nodes);
    k_scatter<<<quad_blocks, B>>>((const int4*)src, (const int4*)dst, n_quads,
                                  src, dst, n_edges);

    int64_t total_threads = (int64_t)n_nodes * 32;
    int gather_blocks = (int)((total_threads + B - 1) / B);
    k_gather<<<gather_blocks, B>>>(weight4, cj, ci, out4, n_nodes);
}